// round 7
// baseline (speedup 1.0000x reference)
#include <cuda_runtime.h>
#include <cuda_bf16.h>
#include <cstdint>

#define DINLINE __device__ __forceinline__

static constexpr int MAXN = 2048;
static constexpr int FIN  = 128;

// ---- scratch (device globals; no allocation allowed) ----
__device__ __align__(16) __nv_bfloat16 g_Wbf[2][1152][128]; // [hi/lo][c][k] N-major
__device__ __align__(16) float g_Cs[MAXN * 1024];           // spline GEMM out [n][1024]
__device__ unsigned char g_cflp[MAXN * FIN];                // [n][i] (linear in i)

// ---------------- PTX helpers ----------------
DINLINE uint32_t smem_u32(const void* p) {
    uint32_t a;
    asm("{ .reg .u64 t; cvta.to.shared.u64 t, %1; cvt.u32.u64 %0, t; }" : "=r"(a) : "l"(p));
    return a;
}
DINLINE void cp16(uint32_t s, const void* g) {
    asm volatile("cp.async.cg.shared.global [%0], [%1], 16;" :: "r"(s), "l"(g));
}
DINLINE void cp_commit() { asm volatile("cp.async.commit_group;"); }
template <int N_> DINLINE void cp_wait() {
    asm volatile("cp.async.wait_group %0;" :: "n"(N_));
}
DINLINE void ldsm_x4(uint32_t& r0, uint32_t& r1, uint32_t& r2, uint32_t& r3, uint32_t addr) {
    asm volatile("ldmatrix.sync.aligned.m8n8.x4.shared.b16 {%0,%1,%2,%3}, [%4];"
                 : "=r"(r0), "=r"(r1), "=r"(r2), "=r"(r3) : "r"(addr));
}
DINLINE void mma16816(float* d, const uint32_t* a, const uint32_t* b) {
    asm volatile(
        "mma.sync.aligned.m16n8k16.row.col.f32.bf16.bf16.f32 "
        "{%0,%1,%2,%3}, {%4,%5,%6,%7}, {%8,%9}, {%0,%1,%2,%3};"
        : "+f"(d[0]), "+f"(d[1]), "+f"(d[2]), "+f"(d[3])
        : "r"(a[0]), "r"(a[1]), "r"(a[2]), "r"(a[3]), "r"(b[0]), "r"(b[1]));
}
// pack hi/lo bf16 split of (a,b) -> two u32 words (a in low half)
DINLINE void split2(float a, float b, uint32_t& hw, uint32_t& lw) {
    __nv_bfloat16 ah = __float2bfloat16(a), bh = __float2bfloat16(b);
    __nv_bfloat162 h; h.x = ah; h.y = bh;
    hw = *(uint32_t*)&h;
    __nv_bfloat162 l;
    l.x = __float2bfloat16(a - __bfloat162float(ah));
    l.y = __float2bfloat16(b - __bfloat162float(bh));
    lw = *(uint32_t*)&l;
}

// ---- K1: weight prep only. Grid: [0,8) baseW; [8,136) splineW transpose ----
__global__ void __launch_bounds__(256) k_prep_w(const float* __restrict__ bw,
                                                const float* __restrict__ sw) {
    __shared__ float tile[32][33];
    const int b = blockIdx.x, t = threadIdx.x;
    if (b < 8) {
        int f8 = b * 256 + t;
        int c = f8 >> 4, ch = f8 & 15;
        const float4* wp = (const float4*)(bw + c * 128 + ch * 8);
        float4 w0 = wp[0], w1 = wp[1];
        float wv[8] = {w0.x, w0.y, w0.z, w0.w, w1.x, w1.y, w1.z, w1.w};
        uint4 hv, lv;
        split2(wv[0], wv[1], hv.x, lv.x);
        split2(wv[2], wv[3], hv.y, lv.y);
        split2(wv[4], wv[5], hv.z, lv.z);
        split2(wv[6], wv[7], hv.w, lv.w);
        *(uint4*)&g_Wbf[0][c][ch * 8] = hv;
        *(uint4*)&g_Wbf[1][c][ch * 8] = lv;
    } else {
        int bb = b - 8;                        // 0..127
        int bc = bb >> 2, bi = bb & 3;         // c-tile, i-tile (32 each)
        int tx = t & 31, ty = t >> 5;
#pragma unroll
        for (int iy = 0; iy < 4; ++iy) {
            int il = ty + 8 * iy;
            tile[il][tx] = sw[(bi * 32 + il) * 1024 + bc * 32 + tx];  // coalesced in c
        }
        __syncthreads();
        {
            int cl = t >> 3, ch = t & 7;
            float wv[4];
#pragma unroll
            for (int e = 0; e < 4; ++e) wv[e] = tile[ch * 4 + e][cl];
            uint2 hv, lv;
            split2(wv[0], wv[1], hv.x, lv.x);
            split2(wv[2], wv[3], hv.y, lv.y);
            int c = 128 + bc * 32 + cl, i = bi * 32 + ch * 4;
            *(uint2*)&g_Wbf[0][c][i] = hv;
            *(uint2*)&g_Wbf[1][c][i] = lv;
        }
    }
}

// ---- in-GEMM activation staging: thread t -> row=t>>1, half=t&1 (64 k-values) ----
template <int SEL, bool WCF>
DINLINE void stage_A(char* smem, const float* __restrict__ x, int m0, int tid) {
    const int row = tid >> 1, half = tid & 1;
    const float* xrow = x + (m0 + row) * 128 + half * 64;
    const float s6 = 0.16666666666666666f;
#pragma unroll
    for (int qq = 0; qq < 8; ++qq) {
        float4 a0 = *(const float4*)(xrow + qq * 8);
        float4 a1 = *(const float4*)(xrow + qq * 8 + 4);
        float xv[8] = {a0.x, a0.y, a0.z, a0.w, a1.x, a1.y, a1.z, a1.w};
        float v[8];
        uint32_t cfb[8];
#pragma unroll
        for (int e = 0; e < 8; ++e) {
            float xe = xv[e];
            if (SEL == 0) {
                v[e] = xe / (1.0f + __expf(-xe));
            } else {
                float xn = fminf(fmaxf(xe, -1.0f), 1.0f);
                float tt = (xn + 2.2f) * 2.5f;
                float fl = floorf(tt);
                float u  = tt - fl;
                int ii = (int)fl; ii = ii < 3 ? 3 : (ii > 7 ? 7 : ii);
                float u2 = u * u;
                if (SEL == 1) v[e] = s6 * (1.0f + u * (-3.0f + u * (3.0f - u)));
                if (SEL == 2) v[e] = s6 * (4.0f + u2 * (3.0f * u - 6.0f));
                if (SEL == 3) v[e] = s6 * (1.0f + u * (3.0f + u * (3.0f - 3.0f * u)));
                if (SEL == 4) v[e] = s6 * (u2 * u);
                if (WCF) cfb[e] = (uint32_t)(ii - 3);
            }
        }
        uint4 hv, lv;
        split2(v[0], v[1], hv.x, lv.x);
        split2(v[2], v[3], hv.y, lv.y);
        split2(v[4], v[5], hv.z, lv.z);
        split2(v[6], v[7], hv.w, lv.w);
        int q  = half * 8 + qq;         // hi chunk 0..15
        int ql = q + 16;                // lo chunk 16..31
        *(uint4*)(smem + row * 512 + (((q  & 24) | ((q  ^ row) & 7)) * 16)) = hv;
        *(uint4*)(smem + row * 512 + (((ql & 24) | ((ql ^ row) & 7)) * 16)) = lv;
        if (WCF) {
            uint2 cw;
            cw.x = cfb[0] | (cfb[1] << 8) | (cfb[2] << 16) | (cfb[3] << 24);
            cw.y = cfb[4] | (cfb[5] << 8) | (cfb[6] << 16) | (cfb[7] << 24);
            *(uint2*)(g_cflp + (m0 + row) * 128 + half * 64 + qq * 8) = cw;
        }
    }
}

// ---- K2: fused act + HMMA GEMM. grid (M/128, 9), 256 thr ----
DINLINE void gemm_pass(uint32_t sb, int a_chunk, uint32_t w_off,
                       int a_lrow, int a_lsel, int b_lrow0, int b_lsel,
                       float (&acc)[4][4][4]) {
#pragma unroll
    for (int ks = 0; ks < 8; ++ks) {
        uint32_t af[4][4];
#pragma unroll
        for (int mt = 0; mt < 4; ++mt) {
            int row = a_lrow + mt * 16;
            int q = a_chunk + ks * 2 + a_lsel;
            uint32_t addr = sb + row * 512 + (((q & 24) | ((q ^ row) & 7)) * 16);
            ldsm_x4(af[mt][0], af[mt][1], af[mt][2], af[mt][3], addr);
        }
        uint32_t bf[4][2];
#pragma unroll
        for (int h = 0; h < 2; ++h) {
            int row = b_lrow0 + h * 16;
            int q = ks * 2 + b_lsel;
            uint32_t addr = sb + 65536 + w_off + row * 256 + (((q & 8) | ((q ^ row) & 7)) * 16);
            uint32_t r0, r1, r2, r3;
            ldsm_x4(r0, r1, r2, r3, addr);
            bf[h * 2][0] = r0;     bf[h * 2][1] = r1;
            bf[h * 2 + 1][0] = r2; bf[h * 2 + 1][1] = r3;
        }
#pragma unroll
        for (int mt = 0; mt < 4; ++mt)
#pragma unroll
            for (int nt = 0; nt < 4; ++nt)
                mma16816(acc[mt][nt], af[mt], bf[nt]);
    }
}

__global__ void __launch_bounds__(256) k_gemm_mma(const float* __restrict__ x,
                                                  float* __restrict__ out) {
    extern __shared__ __align__(128) char smem[];
    const uint32_t sb = smem_u32(smem);
    const int tid = threadIdx.x, lane = tid & 31, wid = tid >> 5;
    const int m0 = blockIdx.x * 128, ct = blockIdx.y;

    // stage W hi (group0), W lo (group1) via cp.async — overlaps with act compute below
#pragma unroll
    for (int it = 0; it < 8; ++it) {
        int idx = it * 256 + tid;
        int row = idx >> 4, q = idx & 15;
        cp16(sb + 65536 + row * 256 + (((q & 8) | ((q ^ row) & 7)) * 16),
             &g_Wbf[0][ct * 128 + row][q * 8]);
    }
    cp_commit();
#pragma unroll
    for (int it = 0; it < 8; ++it) {
        int idx = it * 256 + tid;
        int row = idx >> 4, q = idx & 15;
        cp16(sb + 65536 + 32768 + row * 256 + (((q & 8) | ((q ^ row) & 7)) * 16),
             &g_Wbf[1][ct * 128 + row][q * 8]);
    }
    cp_commit();

    // compute A tile (act + hi/lo split) straight into swizzled smem
    switch (ct) {
        case 0: stage_A<0, false>(smem, x, m0, tid); break;
        case 1: stage_A<1, true >(smem, x, m0, tid); break;
        case 2: stage_A<1, false>(smem, x, m0, tid); break;
        case 3: case 4: stage_A<2, false>(smem, x, m0, tid); break;
        case 5: case 6: stage_A<3, false>(smem, x, m0, tid); break;
        default: stage_A<4, false>(smem, x, m0, tid); break;
    }

    const int wm = wid >> 2, wn = wid & 3;
    float acc[4][4][4];
#pragma unroll
    for (int i = 0; i < 4; ++i)
#pragma unroll
        for (int j = 0; j < 4; ++j)
#pragma unroll
            for (int k = 0; k < 4; ++k) acc[i][j][k] = 0.0f;

    const int a_lrow = wm * 64 + (lane & 15);
    const int a_lsel = lane >> 4;
    const int b_lrow0 = wn * 32 + ((lane >> 4) << 3) + (lane & 7);
    const int b_lsel = (lane >> 3) & 1;

    cp_wait<1>();
    __syncthreads();                    // A smem written + W_hi landed
    gemm_pass(sb, 0, 0, a_lrow, a_lsel, b_lrow0, b_lsel, acc);      // hi*hi
    cp_wait<0>();
    __syncthreads();
    gemm_pass(sb, 16, 0, a_lrow, a_lsel, b_lrow0, b_lsel, acc);     // lo*hi
    gemm_pass(sb, 0, 32768, a_lrow, a_lsel, b_lrow0, b_lsel, acc);  // hi*lo

    const int er = lane >> 2, ec = (lane & 3) * 2;
    if (ct == 0) {
#pragma unroll
        for (int mt = 0; mt < 4; ++mt)
#pragma unroll
            for (int nt = 0; nt < 4; ++nt) {
                int row = m0 + wm * 64 + mt * 16 + er;
                int col = wn * 32 + nt * 8 + ec;
                *(float2*)&out[row * 128 + col]       = make_float2(acc[mt][nt][0], acc[mt][nt][1]);
                *(float2*)&out[(row + 8) * 128 + col] = make_float2(acc[mt][nt][2], acc[mt][nt][3]);
            }
    } else {
#pragma unroll
        for (int mt = 0; mt < 4; ++mt)
#pragma unroll
            for (int nt = 0; nt < 4; ++nt) {
                int row = m0 + wm * 64 + mt * 16 + er;
                int col = (ct - 1) * 128 + wn * 32 + nt * 8 + ec;
                *(float2*)&g_Cs[row * 1024 + col]       = make_float2(acc[mt][nt][0], acc[mt][nt][1]);
                *(float2*)&g_Cs[(row + 8) * 1024 + col] = make_float2(acc[mt][nt][2], acc[mt][nt][3]);
            }
    }
}

// ---- K3: finalize. out[n,o] += sum_jp Cs[n, jp*256 + q*8 + cfl[n, jp*32+q] + r2] ----
__global__ void __launch_bounds__(256) k_final(float* __restrict__ out) {
    int idx = blockIdx.x * 256 + threadIdx.x;
    int n = idx >> 7, o = idx & 127;
    int q = o >> 2, r2 = o & 3;
    float acc = out[idx];
    const unsigned char* cf = g_cflp + n * 128 + q;
    const float* Cs = g_Cs + n * 1024 + q * 8 + r2;
    float t0 = Cs[cf[0]];
    float t1 = Cs[256 + cf[32]];
    float t2 = Cs[512 + cf[64]];
    float t3 = Cs[768 + cf[96]];
    out[idx] = acc + (t0 + t1) + (t2 + t3);
}

extern "C" void kernel_launch(void* const* d_in, const int* in_sizes, int n_in,
                              void* d_out, int out_size) {
    const float* x  = (const float*)d_in[0];
    const float* bw = (const float*)d_in[1];
    const float* sw = (const float*)d_in[2];
    float* out = (float*)d_out;
    int N = in_sizes[0] / FIN;
    if (N > MAXN) N = MAXN;

    const int smem = 65536 + 65536;  // 128 KB
    cudaFuncSetAttribute(k_gemm_mma, cudaFuncAttributeMaxDynamicSharedMemorySize, smem);

    k_prep_w<<<136, 256>>>(bw, sw);
    dim3 grid(N / 128, 9);
    k_gemm_mma<<<grid, 256, smem>>>(x, out);
    k_final<<<(N * FIN) / 256, 256>>>(out);
}

// round 8
// speedup vs baseline: 1.1194x; 1.1194x over previous
#include <cuda_runtime.h>
#include <cuda_bf16.h>
#include <cstdint>

#define DINLINE __device__ __forceinline__

static constexpr int MAXN = 2048;
static constexpr int FIN  = 128;

// ---- scratch (device globals; no allocation allowed) ----
__device__ __align__(16) __nv_bfloat16 g_Abf[5][MAXN][256]; // [sel][n][0:128)=hi,[128:256)=lo
__device__ __align__(16) __nv_bfloat16 g_Wbf[2][1152][128]; // [hi/lo][c][k] N-major
__device__ __align__(16) float g_Cs[MAXN * 1024];           // spline GEMM out [n][1024]
__device__ unsigned char g_cflp[MAXN * FIN];                // planar [n][jp][q]

// ---------------- PTX helpers ----------------
DINLINE uint32_t smem_u32(const void* p) {
    uint32_t a;
    asm("{ .reg .u64 t; cvta.to.shared.u64 t, %1; cvt.u32.u64 %0, t; }" : "=r"(a) : "l"(p));
    return a;
}
DINLINE void cp16(uint32_t s, const void* g) {
    asm volatile("cp.async.cg.shared.global [%0], [%1], 16;" :: "r"(s), "l"(g));
}
DINLINE void cp_commit() { asm volatile("cp.async.commit_group;"); }
template <int N_> DINLINE void cp_wait() {
    asm volatile("cp.async.wait_group %0;" :: "n"(N_));
}
DINLINE void ldsm_x4(uint32_t& r0, uint32_t& r1, uint32_t& r2, uint32_t& r3, uint32_t addr) {
    asm volatile("ldmatrix.sync.aligned.m8n8.x4.shared.b16 {%0,%1,%2,%3}, [%4];"
                 : "=r"(r0), "=r"(r1), "=r"(r2), "=r"(r3) : "r"(addr));
}
DINLINE void mma16816(float* d, const uint32_t* a, const uint32_t* b) {
    asm volatile(
        "mma.sync.aligned.m16n8k16.row.col.f32.bf16.bf16.f32 "
        "{%0,%1,%2,%3}, {%4,%5,%6,%7}, {%8,%9}, {%0,%1,%2,%3};"
        : "+f"(d[0]), "+f"(d[1]), "+f"(d[2]), "+f"(d[3])
        : "r"(a[0]), "r"(a[1]), "r"(a[2]), "r"(a[3]), "r"(b[0]), "r"(b[1]));
}
// pack hi/lo bf16 split of (a,b) -> two u32 words (a in low half)
DINLINE void split2(float a, float b, uint32_t& hw, uint32_t& lw) {
    __nv_bfloat16 ah = __float2bfloat16(a), bh = __float2bfloat16(b);
    __nv_bfloat162 h; h.x = ah; h.y = bh;
    hw = *(uint32_t*)&h;
    __nv_bfloat162 l;
    l.x = __float2bfloat16(a - __bfloat162float(ah));
    l.y = __float2bfloat16(b - __bfloat162float(bh));
    lw = *(uint32_t*)&l;
}

// ---- K1: all prep (R6, proven). Grid: [0,PA4) act; [PA4,PA4+8) baseW; then 128 splineW ----
__global__ void __launch_bounds__(256) k_prep(const float* __restrict__ x,
                                              const float* __restrict__ bw,
                                              const float* __restrict__ sw,
                                              int PA4) {
    __shared__ float tile[32][33];
    const int b = blockIdx.x, t = threadIdx.x;
    if (b < PA4) {
        int idx4 = b * 256 + t;
        int n = idx4 >> 5, c4 = idx4 & 31;
        float4 x0 = *(const float4*)(x + n * 128 + c4 * 4);
        float xv[4] = {x0.x, x0.y, x0.z, x0.w};
        float v[5][4];
        uint32_t cfb[4];
        const float s6 = 0.16666666666666666f;
#pragma unroll
        for (int e = 0; e < 4; ++e) {
            float xe = xv[e];
            v[0][e] = xe / (1.0f + __expf(-xe));
            float xn = fminf(fmaxf(xe, -1.0f), 1.0f);
            float tt = (xn + 2.2f) * 2.5f;
            float fl = floorf(tt);
            float u  = tt - fl;
            int ii = (int)fl; ii = ii < 3 ? 3 : (ii > 7 ? 7 : ii);
            float u2 = u * u;
            v[1][e] = s6 * (1.0f + u * (-3.0f + u * (3.0f - u)));
            v[2][e] = s6 * (4.0f + u2 * (3.0f * u - 6.0f));
            v[3][e] = s6 * (1.0f + u * (3.0f + u * (3.0f - 3.0f * u)));
            v[4][e] = s6 * (u2 * u);
            cfb[e] = (uint32_t)(ii - 3);
        }
#pragma unroll
        for (int s = 0; s < 5; ++s) {
            uint2 hv, lv;
            split2(v[s][0], v[s][1], hv.x, lv.x);
            split2(v[s][2], v[s][3], hv.y, lv.y);
            *(uint2*)&g_Abf[s][n][c4 * 4]       = hv;
            *(uint2*)&g_Abf[s][n][128 + c4 * 4] = lv;
        }
        uint32_t cw = cfb[0] | (cfb[1] << 8) | (cfb[2] << 16) | (cfb[3] << 24);
        *(uint32_t*)(g_cflp + n * 128 + (c4 >> 3) * 32 + (c4 & 7) * 4) = cw;
    } else if (b < PA4 + 8) {
        int f8 = (b - PA4) * 256 + t;
        int c = f8 >> 4, ch = f8 & 15;
        const float4* wp = (const float4*)(bw + c * 128 + ch * 8);
        float4 w0 = wp[0], w1 = wp[1];
        float wv[8] = {w0.x, w0.y, w0.z, w0.w, w1.x, w1.y, w1.z, w1.w};
        uint4 hv, lv;
        split2(wv[0], wv[1], hv.x, lv.x);
        split2(wv[2], wv[3], hv.y, lv.y);
        split2(wv[4], wv[5], hv.z, lv.z);
        split2(wv[6], wv[7], hv.w, lv.w);
        *(uint4*)&g_Wbf[0][c][ch * 8] = hv;
        *(uint4*)&g_Wbf[1][c][ch * 8] = lv;
    } else {
        int bb = b - PA4 - 8;
        int bc = bb >> 2, bi = bb & 3;
        int tx = t & 31, ty = t >> 5;
#pragma unroll
        for (int iy = 0; iy < 4; ++iy) {
            int il = ty + 8 * iy;
            tile[il][tx] = sw[(bi * 32 + il) * 1024 + bc * 32 + tx];
        }
        __syncthreads();
        {
            int cl = t >> 3, ch = t & 7;
            float wv[4];
#pragma unroll
            for (int e = 0; e < 4; ++e) wv[e] = tile[ch * 4 + e][cl];
            uint2 hv, lv;
            split2(wv[0], wv[1], hv.x, lv.x);
            split2(wv[2], wv[3], hv.y, lv.y);
            int c = 128 + bc * 32 + cl, i = bi * 32 + ch * 4;
            *(uint2*)&g_Wbf[0][c][i] = hv;
            *(uint2*)&g_Wbf[1][c][i] = lv;
        }
    }
}

// ---- K2: HMMA GEMM, M-tile 64, 2 CTAs/SM. grid (M/64, 9), 256 thr ----
// smem: A 64x512B (hi|lo chunks) @0 (32KB); W hi @32768, W lo @65536 (each 32KB). 96KB total.
DINLINE void gemm_pass(uint32_t sb, int a_chunk, uint32_t w_off,
                       int a_lrow, int a_lsel, int b_lrow0, int b_lsel,
                       float (&acc)[2][4][4]) {
#pragma unroll
    for (int ks = 0; ks < 8; ++ks) {
        uint32_t af[2][4];
#pragma unroll
        for (int mt = 0; mt < 2; ++mt) {
            int row = a_lrow + mt * 16;
            int q = a_chunk + ks * 2 + a_lsel;
            uint32_t addr = sb + row * 512 + (((q & 24) | ((q ^ row) & 7)) * 16);
            ldsm_x4(af[mt][0], af[mt][1], af[mt][2], af[mt][3], addr);
        }
        uint32_t bf[4][2];
#pragma unroll
        for (int h = 0; h < 2; ++h) {
            int row = b_lrow0 + h * 16;
            int q = ks * 2 + b_lsel;
            uint32_t addr = sb + 32768 + w_off + row * 256 + (((q & 8) | ((q ^ row) & 7)) * 16);
            uint32_t r0, r1, r2, r3;
            ldsm_x4(r0, r1, r2, r3, addr);
            bf[h * 2][0] = r0;     bf[h * 2][1] = r1;
            bf[h * 2 + 1][0] = r2; bf[h * 2 + 1][1] = r3;
        }
#pragma unroll
        for (int mt = 0; mt < 2; ++mt)
#pragma unroll
            for (int nt = 0; nt < 4; ++nt)
                mma16816(acc[mt][nt], af[mt], bf[nt]);
    }
}

__global__ void __launch_bounds__(256) k_gemm_mma(float* __restrict__ out) {
    extern __shared__ __align__(128) char smem[];
    const uint32_t sb = smem_u32(smem);
    const int tid = threadIdx.x, lane = tid & 31, wid = tid >> 5;
    const int m0 = blockIdx.x * 64, ct = blockIdx.y;
    const int sel = (ct == 0) ? 0 : 1 + ((ct - 1) >> 1);

    const __nv_bfloat16* Asrc = &g_Abf[sel][m0][0];
    // group 0: A_hi (64 rows x 16 chunks) + W_hi (128 rows x 16 chunks)
#pragma unroll
    for (int it = 0; it < 4; ++it) {
        int idx = it * 256 + tid;
        int row = idx >> 4, q = idx & 15;
        cp16(sb + row * 512 + (((q & 24) | ((q ^ row) & 7)) * 16), Asrc + row * 256 + q * 8);
    }
#pragma unroll
    for (int it = 0; it < 8; ++it) {
        int idx = it * 256 + tid;
        int row = idx >> 4, q = idx & 15;
        cp16(sb + 32768 + row * 256 + (((q & 8) | ((q ^ row) & 7)) * 16),
             &g_Wbf[0][ct * 128 + row][q * 8]);
    }
    cp_commit();
    // group 1: A_lo + W_lo
#pragma unroll
    for (int it = 0; it < 4; ++it) {
        int idx = it * 256 + tid;
        int row = idx >> 4, q = 16 + (idx & 15);
        cp16(sb + row * 512 + (((q & 24) | ((q ^ row) & 7)) * 16), Asrc + row * 256 + q * 8);
    }
#pragma unroll
    for (int it = 0; it < 8; ++it) {
        int idx = it * 256 + tid;
        int row = idx >> 4, q = idx & 15;
        cp16(sb + 65536 + row * 256 + (((q & 8) | ((q ^ row) & 7)) * 16),
             &g_Wbf[1][ct * 128 + row][q * 8]);
    }
    cp_commit();

    const int wm = wid >> 2, wn = wid & 3;     // warp tile: 32 rows x 32 cols
    float acc[2][4][4];
#pragma unroll
    for (int i = 0; i < 2; ++i)
#pragma unroll
        for (int j = 0; j < 4; ++j)
#pragma unroll
            for (int k = 0; k < 4; ++k) acc[i][j][k] = 0.0f;

    const int a_lrow = wm * 32 + (lane & 15);
    const int a_lsel = lane >> 4;
    const int b_lrow0 = wn * 32 + ((lane >> 4) << 3) + (lane & 7);
    const int b_lsel = (lane >> 3) & 1;

    cp_wait<1>();
    __syncthreads();
    gemm_pass(sb, 0, 0, a_lrow, a_lsel, b_lrow0, b_lsel, acc);      // hi*hi
    cp_wait<0>();
    __syncthreads();
    gemm_pass(sb, 16, 0, a_lrow, a_lsel, b_lrow0, b_lsel, acc);     // lo*hi
    gemm_pass(sb, 0, 32768, a_lrow, a_lsel, b_lrow0, b_lsel, acc);  // hi*lo

    const int er = lane >> 2, ec = (lane & 3) * 2;
    if (ct == 0) {
#pragma unroll
        for (int mt = 0; mt < 2; ++mt)
#pragma unroll
            for (int nt = 0; nt < 4; ++nt) {
                int row = m0 + wm * 32 + mt * 16 + er;
                int col = wn * 32 + nt * 8 + ec;
                *(float2*)&out[row * 128 + col]       = make_float2(acc[mt][nt][0], acc[mt][nt][1]);
                *(float2*)&out[(row + 8) * 128 + col] = make_float2(acc[mt][nt][2], acc[mt][nt][3]);
            }
    } else {
#pragma unroll
        for (int mt = 0; mt < 2; ++mt)
#pragma unroll
            for (int nt = 0; nt < 4; ++nt) {
                int row = m0 + wm * 32 + mt * 16 + er;
                int col = (ct - 1) * 128 + wn * 32 + nt * 8 + ec;
                *(float2*)&g_Cs[row * 1024 + col]       = make_float2(acc[mt][nt][0], acc[mt][nt][1]);
                *(float2*)&g_Cs[(row + 8) * 1024 + col] = make_float2(acc[mt][nt][2], acc[mt][nt][3]);
            }
    }
}

// ---- K3: finalize ----
__global__ void __launch_bounds__(256) k_final(float* __restrict__ out) {
    int idx = blockIdx.x * 256 + threadIdx.x;
    int n = idx >> 7, o = idx & 127;
    int q = o >> 2, r2 = o & 3;
    float acc = out[idx];
    const unsigned char* cf = g_cflp + n * 128 + q;
    const float* Cs = g_Cs + n * 1024 + q * 8 + r2;
    float t0 = Cs[cf[0]];
    float t1 = Cs[256 + cf[32]];
    float t2 = Cs[512 + cf[64]];
    float t3 = Cs[768 + cf[96]];
    out[idx] = acc + (t0 + t1) + (t2 + t3);
}

extern "C" void kernel_launch(void* const* d_in, const int* in_sizes, int n_in,
                              void* d_out, int out_size) {
    const float* x  = (const float*)d_in[0];
    const float* bw = (const float*)d_in[1];
    const float* sw = (const float*)d_in[2];
    float* out = (float*)d_out;
    int N = in_sizes[0] / FIN;
    if (N > MAXN) N = MAXN;

    const int smem = 32768 + 65536;  // 96 KB -> 2 CTAs/SM
    cudaFuncSetAttribute(k_gemm_mma, cudaFuncAttributeMaxDynamicSharedMemorySize, smem);

    int PA4 = (N * FIN) / 1024;
    k_prep<<<PA4 + 8 + 128, 256>>>(x, bw, sw, PA4);
    dim3 grid(N / 64, 9);
    k_gemm_mma<<<grid, 256, smem>>>(out);
    k_final<<<(N * FIN) / 256, 256>>>(out);
}

// round 10
// speedup vs baseline: 1.4742x; 1.3170x over previous
#include <cuda_runtime.h>
#include <cuda_fp16.h>
#include <cstdint>

#define DINLINE __device__ __forceinline__

static constexpr int MAXN = 2048;
static constexpr int FIN  = 128;

// ---- scratch (device globals; no allocation allowed) ----
__device__ __align__(16) __half g_Ah[5][MAXN][128];   // [sel][n][i] fp16
__device__ __align__(16) __half g_Wh[1152][128];      // [c][k] fp16, N-major
__device__ __align__(16) float g_Cs[MAXN * 1024];     // spline GEMM out [n][1024]
__device__ unsigned char g_cflp[MAXN * FIN];          // planar [n][jp][q]

// ---------------- PTX helpers ----------------
DINLINE uint32_t smem_u32(const void* p) {
    uint32_t a;
    asm("{ .reg .u64 t; cvta.to.shared.u64 t, %1; cvt.u32.u64 %0, t; }" : "=r"(a) : "l"(p));
    return a;
}
DINLINE void cp16(uint32_t s, const void* g) {
    asm volatile("cp.async.cg.shared.global [%0], [%1], 16;" :: "r"(s), "l"(g));
}
DINLINE void cp_commit() { asm volatile("cp.async.commit_group;"); }
template <int N_> DINLINE void cp_wait() {
    asm volatile("cp.async.wait_group %0;" :: "n"(N_));
}
DINLINE void ldsm_x4(uint32_t& r0, uint32_t& r1, uint32_t& r2, uint32_t& r3, uint32_t addr) {
    asm volatile("ldmatrix.sync.aligned.m8n8.x4.shared.b16 {%0,%1,%2,%3}, [%4];"
                 : "=r"(r0), "=r"(r1), "=r"(r2), "=r"(r3) : "r"(addr));
}
DINLINE void mma16816(float* d, const uint32_t* a, const uint32_t* b) {
    asm volatile(
        "mma.sync.aligned.m16n8k16.row.col.f32.f16.f16.f32 "
        "{%0,%1,%2,%3}, {%4,%5,%6,%7}, {%8,%9}, {%0,%1,%2,%3};"
        : "+f"(d[0]), "+f"(d[1]), "+f"(d[2]), "+f"(d[3])
        : "r"(a[0]), "r"(a[1]), "r"(a[2]), "r"(a[3]), "r"(b[0]), "r"(b[1]));
}
DINLINE uint32_t pack_h2(float a, float b) {
    uint32_t r;
    asm("cvt.rn.f16x2.f32 %0, %1, %2;" : "=r"(r) : "f"(b), "f"(a));
    return r;
}

// ---- K1: all prep. Grid: [0,PA4) act (4 elems/thr); [PA4,PA4+8) baseW; then 128 splineW ----
__global__ void __launch_bounds__(256) k_prep(const float* __restrict__ x,
                                              const float* __restrict__ bw,
                                              const float* __restrict__ sw,
                                              int PA4) {
    __shared__ float tile[32][33];
    const int b = blockIdx.x, t = threadIdx.x;
    if (b < PA4) {
        int idx4 = b * 256 + t;
        int n = idx4 >> 5, c4 = idx4 & 31;
        float4 x0 = *(const float4*)(x + n * 128 + c4 * 4);
        float xv[4] = {x0.x, x0.y, x0.z, x0.w};
        float v[5][4];
        uint32_t cfb[4];
        const float s6 = 0.16666666666666666f;
#pragma unroll
        for (int e = 0; e < 4; ++e) {
            float xe = xv[e];
            v[0][e] = xe / (1.0f + __expf(-xe));
            float xn = fminf(fmaxf(xe, -1.0f), 1.0f);
            float tt = (xn + 2.2f) * 2.5f;
            float fl = floorf(tt);
            float u  = tt - fl;
            int ii = (int)fl; ii = ii < 3 ? 3 : (ii > 7 ? 7 : ii);
            float u2 = u * u;
            v[1][e] = s6 * (1.0f + u * (-3.0f + u * (3.0f - u)));
            v[2][e] = s6 * (4.0f + u2 * (3.0f * u - 6.0f));
            v[3][e] = s6 * (1.0f + u * (3.0f + u * (3.0f - 3.0f * u)));
            v[4][e] = s6 * (u2 * u);
            cfb[e] = (uint32_t)(ii - 3);
        }
#pragma unroll
        for (int s = 0; s < 5; ++s) {
            uint2 hv;
            hv.x = pack_h2(v[s][0], v[s][1]);
            hv.y = pack_h2(v[s][2], v[s][3]);
            *(uint2*)&g_Ah[s][n][c4 * 4] = hv;
        }
        uint32_t cw = cfb[0] | (cfb[1] << 8) | (cfb[2] << 16) | (cfb[3] << 24);
        *(uint32_t*)(g_cflp + n * 128 + (c4 >> 3) * 32 + (c4 & 7) * 4) = cw;
    } else if (b < PA4 + 8) {
        int f8 = (b - PA4) * 256 + t;
        int c = f8 >> 4, ch = f8 & 15;
        const float4* wp = (const float4*)(bw + c * 128 + ch * 8);
        float4 w0 = wp[0], w1 = wp[1];
        uint4 hv;
        hv.x = pack_h2(w0.x, w0.y);
        hv.y = pack_h2(w0.z, w0.w);
        hv.z = pack_h2(w1.x, w1.y);
        hv.w = pack_h2(w1.z, w1.w);
        *(uint4*)&g_Wh[c][ch * 8] = hv;
    } else {
        int bb = b - PA4 - 8;
        int bc = bb >> 2, bi = bb & 3;
        int tx = t & 31, ty = t >> 5;
#pragma unroll
        for (int iy = 0; iy < 4; ++iy) {
            int il = ty + 8 * iy;
            tile[il][tx] = sw[(bi * 32 + il) * 1024 + bc * 32 + tx];
        }
        __syncthreads();
        {
            int cl = t >> 3, ch = t & 7;
            uint2 hv;
            hv.x = pack_h2(tile[ch * 4 + 0][cl], tile[ch * 4 + 1][cl]);
            hv.y = pack_h2(tile[ch * 4 + 2][cl], tile[ch * 4 + 3][cl]);
            int c = 128 + bc * 32 + cl, i = bi * 32 + ch * 4;
            *(uint2*)&g_Wh[c][i] = hv;
        }
    }
}

// ---- K2: fp16 HMMA GEMM, single pass, k-halved staging pipeline. grid (M/128, 9), 256 thr ----
// smem: A 128x256B @0 (32KB, chunks q=0..15), W 128x256B @32768 (32KB).
DINLINE void gemm_pass(uint32_t sb, int ks0, int ks1,
                       int a_lrow, int a_lsel, int b_lrow0, int b_lsel,
                       float (&acc)[4][4][4]) {
#pragma unroll
    for (int ks = ks0; ks < ks1; ++ks) {
        uint32_t af[4][4];
#pragma unroll
        for (int mt = 0; mt < 4; ++mt) {
            int row = a_lrow + mt * 16;
            int q = ks * 2 + a_lsel;
            uint32_t addr = sb + row * 256 + (((q & 8) | ((q ^ row) & 7)) * 16);
            ldsm_x4(af[mt][0], af[mt][1], af[mt][2], af[mt][3], addr);
        }
        uint32_t bf[4][2];
#pragma unroll
        for (int h = 0; h < 2; ++h) {
            int row = b_lrow0 + h * 16;
            int q = ks * 2 + b_lsel;
            uint32_t addr = sb + 32768 + row * 256 + (((q & 8) | ((q ^ row) & 7)) * 16);
            uint32_t r0, r1, r2, r3;
            ldsm_x4(r0, r1, r2, r3, addr);
            bf[h * 2][0] = r0;     bf[h * 2][1] = r1;
            bf[h * 2 + 1][0] = r2; bf[h * 2 + 1][1] = r3;
        }
#pragma unroll
        for (int mt = 0; mt < 4; ++mt)
#pragma unroll
            for (int nt = 0; nt < 4; ++nt)
                mma16816(acc[mt][nt], af[mt], bf[nt]);
    }
}

__global__ void __launch_bounds__(256) k_gemm_mma(float* __restrict__ out) {
    extern __shared__ __align__(128) char smem[];
    const uint32_t sb = smem_u32(smem);
    const int tid = threadIdx.x, lane = tid & 31, wid = tid >> 5;
    const int m0 = blockIdx.x * 128, ct = blockIdx.y;
    const int sel = (ct == 0) ? 0 : 1 + ((ct - 1) >> 1);

    const __half* Asrc = &g_Ah[sel][m0][0];
    // group 0: k chunks 0..7 of A and W
#pragma unroll
    for (int it = 0; it < 4; ++it) {
        int idx = it * 256 + tid;
        int row = idx >> 3, q = idx & 7;
        cp16(sb + row * 256 + (((q & 8) | ((q ^ row) & 7)) * 16), Asrc + row * 128 + q * 8);
    }
#pragma unroll
    for (int it = 0; it < 4; ++it) {
        int idx = it * 256 + tid;
        int row = idx >> 3, q = idx & 7;
        cp16(sb + 32768 + row * 256 + (((q & 8) | ((q ^ row) & 7)) * 16),
             &g_Wh[ct * 128 + row][q * 8]);
    }
    cp_commit();
    // group 1: k chunks 8..15
#pragma unroll
    for (int it = 0; it < 4; ++it) {
        int idx = it * 256 + tid;
        int row = idx >> 3, q = 8 + (idx & 7);
        cp16(sb + row * 256 + (((q & 8) | ((q ^ row) & 7)) * 16), Asrc + row * 128 + q * 8);
    }
#pragma unroll
    for (int it = 0; it < 4; ++it) {
        int idx = it * 256 + tid;
        int row = idx >> 3, q = 8 + (idx & 7);
        cp16(sb + 32768 + row * 256 + (((q & 8) | ((q ^ row) & 7)) * 16),
             &g_Wh[ct * 128 + row][q * 8]);
    }
    cp_commit();

    const int wm = wid >> 2, wn = wid & 3;     // warp tile: 64 rows x 32 cols
    float acc[4][4][4];
#pragma unroll
    for (int i = 0; i < 4; ++i)
#pragma unroll
        for (int j = 0; j < 4; ++j)
#pragma unroll
            for (int k = 0; k < 4; ++k) acc[i][j][k] = 0.0f;

    const int a_lrow = wm * 64 + (lane & 15);
    const int a_lsel = lane >> 4;
    const int b_lrow0 = wn * 32 + ((lane >> 4) << 3) + (lane & 7);
    const int b_lsel = (lane >> 3) & 1;

    cp_wait<1>();
    __syncthreads();
    gemm_pass(sb, 0, 4, a_lrow, a_lsel, b_lrow0, b_lsel, acc);   // k 0..63
    cp_wait<0>();
    __syncthreads();
    gemm_pass(sb, 4, 8, a_lrow, a_lsel, b_lrow0, b_lsel, acc);   // k 64..127

    const int er = lane >> 2, ec = (lane & 3) * 2;
    if (ct == 0) {
#pragma unroll
        for (int mt = 0; mt < 4; ++mt)
#pragma unroll
            for (int nt = 0; nt < 4; ++nt) {
                int row = m0 + wm * 64 + mt * 16 + er;
                int col = wn * 32 + nt * 8 + ec;
                *(float2*)&out[row * 128 + col]       = make_float2(acc[mt][nt][0], acc[mt][nt][1]);
                *(float2*)&out[(row + 8) * 128 + col] = make_float2(acc[mt][nt][2], acc[mt][nt][3]);
            }
    } else {
#pragma unroll
        for (int mt = 0; mt < 4; ++mt)
#pragma unroll
            for (int nt = 0; nt < 4; ++nt) {
                int row = m0 + wm * 64 + mt * 16 + er;
                int col = (ct - 1) * 128 + wn * 32 + nt * 8 + ec;
                *(float2*)&g_Cs[row * 1024 + col]       = make_float2(acc[mt][nt][0], acc[mt][nt][1]);
                *(float2*)&g_Cs[(row + 8) * 1024 + col] = make_float2(acc[mt][nt][2], acc[mt][nt][3]);
            }
    }
}

// ---- K3: finalize ----
__global__ void __launch_bounds__(256) k_final(float* __restrict__ out) {
    int idx = blockIdx.x * 256 + threadIdx.x;
    int n = idx >> 7, o = idx & 127;
    int q = o >> 2, r2 = o & 3;
    float acc = out[idx];
    const unsigned char* cf = g_cflp + n * 128 + q;
    const float* Cs = g_Cs + n * 1024 + q * 8 + r2;
    float t0 = Cs[cf[0]];
    float t1 = Cs[256 + cf[32]];
    float t2 = Cs[512 + cf[64]];
    float t3 = Cs[768 + cf[96]];
    out[idx] = acc + (t0 + t1) + (t2 + t3);
}

extern "C" void kernel_launch(void* const* d_in, const int* in_sizes, int n_in,
                              void* d_out, int out_size) {
    const float* x  = (const float*)d_in[0];
    const float* bw = (const float*)d_in[1];
    const float* sw = (const float*)d_in[2];
    float* out = (float*)d_out;
    int N = in_sizes[0] / FIN;
    if (N > MAXN) N = MAXN;

    const int smem = 32768 + 32768;  // 64 KB
    cudaFuncSetAttribute(k_gemm_mma, cudaFuncAttributeMaxDynamicSharedMemorySize, smem);

    int PA4 = (N * FIN) / 1024;
    k_prep<<<PA4 + 8 + 128, 256>>>(x, bw, sw, PA4);
    dim3 grid(N / 128, 9);
    k_gemm_mma<<<grid, 256, smem>>>(out);
    k_final<<<(N * FIN) / 256, 256>>>(out);
}